// round 1
// baseline (speedup 1.0000x reference)
#include <cuda_runtime.h>
#include <cuda_bf16.h>
#include <math.h>

#define N 4096
#define D 128
#define ALPHA 10.0f
#define BETA 2.0f
#define BASE 0.5f
#define BIGF 1e30f

// ---------------- device scratch (static: no allocation allowed) ----------------
__device__ float    g_sim[(size_t)N * N];   // 64 MB similarity matrix
__device__ unsigned g_minpos[N];            // order-preserving uint encoding of min positive sim
__device__ unsigned g_maxneg[N];            // order-preserving uint encoding of max negative sim
__device__ float    g_loss[N];              // per-row loss
__device__ int      g_is64;                 // 1 if targets buffer is int64, 0 if int32

// order-preserving float<->uint transforms (unsigned compare == float compare)
__device__ __forceinline__ unsigned f2u(float f) {
    unsigned b = __float_as_uint(f);
    return (b & 0x80000000u) ? ~b : (b | 0x80000000u);
}
__device__ __forceinline__ float u2f(unsigned u) {
    return (u & 0x80000000u) ? __uint_as_float(u ^ 0x80000000u) : __uint_as_float(~u);
}

__device__ __forceinline__ int get_t(const void* p, int i) {
    if (g_is64) return (int)((const long long*)p)[i];
    return ((const int*)p)[i];
}

// ---------------- kernel: detect targets dtype ----------------
// View buffer as int32. If dtype is int64 (targets in [0,64)), every odd word
// (high half) is 0. If int32, odd words are random targets of odd rows —
// probability all 128 are zero is ~64^-128. Read only 1 KB (safe either way).
__global__ void k_detect(const int* __restrict__ t) {
    if (threadIdx.x == 0) {
        int ok = 1;
        #pragma unroll 4
        for (int i = 1; i < 256; i += 2)
            if (t[i] != 0) { ok = 0; break; }
        g_is64 = ok;
    }
}

// ---------------- kernel: init accumulators ----------------
__global__ void k_init() {
    int i = blockIdx.x * 256 + threadIdx.x;
    if (i < N) {
        g_minpos[i] = f2u(BIGF);
        g_maxneg[i] = f2u(-BIGF);
    }
}

// ---------------- kernel: sim = X X^T + fused row min-pos / max-neg ----------------
// 128x128 tile per block, 256 threads, 8x8 micro-tile per thread, K chunked by 32.
__global__ __launch_bounds__(256) void k_gemm(const float* __restrict__ X,
                                              const void* __restrict__ tgt) {
    __shared__ float As[32][128];
    __shared__ float Bs[32][128];

    const int tid = threadIdx.x;
    const int tx = tid & 15;       // 16 col groups
    const int ty = tid >> 4;       // 16 row groups
    const int rowBase = blockIdx.y * 128;
    const int colBase = blockIdx.x * 128;

    float acc[8][8];
    #pragma unroll
    for (int i = 0; i < 8; i++)
        #pragma unroll
        for (int j = 0; j < 8; j++) acc[i][j] = 0.f;

    for (int k0 = 0; k0 < D; k0 += 32) {
        // load 128x32 A-chunk and B-chunk, transposed into [k][m]
        #pragma unroll
        for (int it = 0; it < 4; it++) {
            int v  = tid + it * 256;   // 0..1023 float4 slots
            int r  = v >> 3;           // row 0..127
            int kq = v & 7;            // float4 within 32-wide k chunk
            float4 fa = *reinterpret_cast<const float4*>(&X[(size_t)(rowBase + r) * D + k0 + kq * 4]);
            As[kq * 4 + 0][r] = fa.x; As[kq * 4 + 1][r] = fa.y;
            As[kq * 4 + 2][r] = fa.z; As[kq * 4 + 3][r] = fa.w;
            float4 fb = *reinterpret_cast<const float4*>(&X[(size_t)(colBase + r) * D + k0 + kq * 4]);
            Bs[kq * 4 + 0][r] = fb.x; Bs[kq * 4 + 1][r] = fb.y;
            Bs[kq * 4 + 2][r] = fb.z; Bs[kq * 4 + 3][r] = fb.w;
        }
        __syncthreads();

        #pragma unroll
        for (int k = 0; k < 32; k++) {
            float4 a0 = *reinterpret_cast<const float4*>(&As[k][ty * 8]);
            float4 a1 = *reinterpret_cast<const float4*>(&As[k][ty * 8 + 4]);
            float4 b0 = *reinterpret_cast<const float4*>(&Bs[k][tx * 8]);
            float4 b1 = *reinterpret_cast<const float4*>(&Bs[k][tx * 8 + 4]);
            float a[8] = {a0.x, a0.y, a0.z, a0.w, a1.x, a1.y, a1.z, a1.w};
            float b[8] = {b0.x, b0.y, b0.z, b0.w, b1.x, b1.y, b1.z, b1.w};
            #pragma unroll
            for (int i = 0; i < 8; i++)
                #pragma unroll
                for (int j = 0; j < 8; j++)
                    acc[i][j] = fmaf(a[i], b[j], acc[i][j]);
        }
        __syncthreads();
    }

    // epilogue: store sim + fused min-pos / max-neg per row
    int tr[8], tc[8];
    #pragma unroll
    for (int i = 0; i < 8; i++) tr[i] = get_t(tgt, rowBase + ty * 8 + i);
    #pragma unroll
    for (int j = 0; j < 8; j++) tc[j] = get_t(tgt, colBase + tx * 8 + j);

    #pragma unroll
    for (int i = 0; i < 8; i++) {
        int row = rowBase + ty * 8 + i;
        float minp = BIGF, maxn = -BIGF;
        #pragma unroll
        for (int j = 0; j < 8; j++) {
            float s = acc[i][j];
            if (tr[i] == tc[j]) {
                if (s < 1.0f) minp = fminf(minp, s);   // positive candidate (drops self)
            } else {
                maxn = fmaxf(maxn, s);                  // negative
            }
        }
        // reduce across the 16 tx-threads (contiguous 16-lane groups)
        #pragma unroll
        for (int m = 8; m >= 1; m >>= 1) {
            minp = fminf(minp, __shfl_xor_sync(0xFFFFFFFFu, minp, m, 16));
            maxn = fmaxf(maxn, __shfl_xor_sync(0xFFFFFFFFu, maxn, m, 16));
        }
        if (tx == 0) {
            atomicMin(&g_minpos[row], f2u(minp));
            atomicMax(&g_maxneg[row], f2u(maxn));
        }
        float* dst = &g_sim[(size_t)row * N + colBase + tx * 8];
        reinterpret_cast<float4*>(dst)[0] = make_float4(acc[i][0], acc[i][1], acc[i][2], acc[i][3]);
        reinterpret_cast<float4*>(dst)[1] = make_float4(acc[i][4], acc[i][5], acc[i][6], acc[i][7]);
    }
}

// ---------------- kernel: mining + masked exp sums; one block per row ----------------
__global__ __launch_bounds__(256) void k_mine(const void* __restrict__ tgt,
                                              const float* __restrict__ margin,
                                              const float* __restrict__ weight,
                                              float* __restrict__ out, int out_size) {
    __shared__ int sT[N];                    // 16 KB targets
    const int row = blockIdx.x;
    const int tid = threadIdx.x;

    for (int j = tid; j < N; j += 256) sT[j] = get_t(tgt, j);
    __syncthreads();

    const int   tr   = sT[row];
    const float m    = margin[row];
    const float w    = weight[row];
    const float minp = u2f(g_minpos[row]);
    const float maxn = u2f(g_maxneg[row]);
    const float* srow = &g_sim[(size_t)row * N];

    float ps = 0.f, ns = 0.f;
    int ap = 0, an = 0;

    for (int j = tid; j < N; j += 256) {
        float s = srow[j];
        if (sT[j] == tr) {
            if (s < 1.0f && (maxn - s + m > 0.0f)) {
                ap++;
                ps += __expf(-BETA * (s * w - BASE));
            }
        } else {
            if (s + m - minp > 0.0f) {
                an++;
                ns += __expf(ALPHA * (s * w - BASE));
            }
        }
    }

    // deterministic reduction: butterfly in-warp, then fixed-order across 8 warps
    #pragma unroll
    for (int o = 16; o >= 1; o >>= 1) {
        ps += __shfl_xor_sync(0xFFFFFFFFu, ps, o);
        ns += __shfl_xor_sync(0xFFFFFFFFu, ns, o);
        ap += __shfl_xor_sync(0xFFFFFFFFu, ap, o);
        an += __shfl_xor_sync(0xFFFFFFFFu, an, o);
    }
    __shared__ float rps[8], rns[8];
    __shared__ int   rap[8], ran[8];
    int wid = tid >> 5;
    if ((tid & 31) == 0) { rps[wid] = ps; rns[wid] = ns; rap[wid] = ap; ran[wid] = an; }
    __syncthreads();

    if (tid == 0) {
        float Ps = 0.f, Ns = 0.f; int Ap = 0, An = 0;
        #pragma unroll
        for (int i = 0; i < 8; i++) { Ps += rps[i]; Ns += rns[i]; Ap += rap[i]; An += ran[i]; }
        int valid = (Ap + An) >= 1;
        float li = valid ? ((2.0f / BETA) * log1pf(Ps) + (2.0f / ALPHA) * log1pf(Ns)) : 0.0f;
        g_loss[row] = li;
        if (out_size >= 1 + 2 * N) {
            out[1 + row]     = valid ? (float)Ap : 0.0f;
            out[1 + N + row] = valid ? (float)An : 0.0f;
        }
    }
}

// ---------------- kernel: deterministic loss reduction ----------------
__global__ void k_reduce(float* __restrict__ out, int out_size) {
    __shared__ float s[1024];
    int t = threadIdx.x;
    float v = g_loss[t] + g_loss[t + 1024] + g_loss[t + 2048] + g_loss[t + 3072];
    s[t] = v;
    __syncthreads();
    #pragma unroll
    for (int o = 512; o >= 1; o >>= 1) {
        if (t < o) s[t] += s[t + o];
        __syncthreads();
    }
    if (t == 0 && out_size >= 1) out[0] = s[0] / (float)N;
}

// ---------------- launch ----------------
extern "C" void kernel_launch(void* const* d_in, const int* in_sizes, int n_in,
                              void* d_out, int out_size) {
    const float* X      = (const float*)d_in[0];
    const void*  tgt    = d_in[1];
    const float* margin = (const float*)d_in[2];
    const float* weight = (const float*)d_in[3];
    float* out = (float*)d_out;

    k_detect<<<1, 32>>>((const int*)tgt);
    k_init<<<(N + 255) / 256, 256>>>();
    k_gemm<<<dim3(N / 128, N / 128), 256>>>(X, tgt);
    k_mine<<<N, 256>>>(tgt, margin, weight, out, out_size);
    k_reduce<<<1, 1024>>>(out, out_size);
}

// round 2
// speedup vs baseline: 1.4408x; 1.4408x over previous
#include <cuda_runtime.h>
#include <cuda_bf16.h>
#include <math.h>

#define N 4096
#define D 128
#define ALPHA 10.0f
#define BETA 2.0f
#define BASE 0.5f
#define BIGF 1e30f

// ---------------- device scratch (static: no allocation allowed) ----------------
__device__ float         g_sim[(size_t)N * N];   // 64 MB similarity matrix
__device__ unsigned      g_minpos[N];            // order-preserving uint encoding of min positive sim
__device__ unsigned      g_maxneg[N];            // order-preserving uint encoding of max negative sim
__device__ float         g_loss[N];              // per-row loss
__device__ unsigned char g_t8[N];                // targets as uint8 (64 classes)

// order-preserving float<->uint transforms (unsigned compare == float compare)
__device__ __forceinline__ unsigned f2u(float f) {
    unsigned b = __float_as_uint(f);
    return (b & 0x80000000u) ? ~b : (b | 0x80000000u);
}
__device__ __forceinline__ float u2f(unsigned u) {
    return (u & 0x80000000u) ? __uint_as_float(u ^ 0x80000000u) : __uint_as_float(~u);
}

// ---------------- kernel: detect dtype + convert targets + init accumulators ----------------
// dtype detect: view as int32; if int64 (targets in [0,64)) every odd word is 0.
__global__ void k_prep(const int* __restrict__ t) {
    __shared__ int s64;
    if (threadIdx.x == 0) {
        int ok = 1;
        #pragma unroll 4
        for (int i = 1; i < 256; i += 2)
            if (t[i] != 0) { ok = 0; break; }
        s64 = ok;
    }
    __syncthreads();
    int j = blockIdx.x * 256 + threadIdx.x;
    if (j < N) {
        g_minpos[j] = f2u(BIGF);
        g_maxneg[j] = f2u(-BIGF);
        g_t8[j] = s64 ? (unsigned char)((const long long*)t)[j]
                      : (unsigned char)t[j];
    }
}

// ---------------- kernel: sim = X X^T, upper triangle only, + fused min/max both axes ----------------
// 128x128 tile per block, 256 threads, 8x8 micro-tile per thread, K chunked by 32.
// Each block (bi<=bj) stores its tile normally AND transposed, and updates
// min-pos/max-neg for both its row range (row-direction reduce) and its column
// range (column-direction reduce; valid because sim is symmetric).
__global__ __launch_bounds__(256, 2) void k_gemm(const float* __restrict__ X) {
    __shared__ float As[32][128];
    __shared__ float Bs[32][128];

    const int bi = blockIdx.y;          // block row
    const int bj = blockIdx.x;          // block col
    if (bj < bi) return;                // upper triangle only

    const int tid = threadIdx.x;
    const int tx = tid & 15;            // 16 col groups
    const int ty = tid >> 4;            // 16 row groups
    const int rowBase = bi * 128;
    const int colBase = bj * 128;

    float acc[8][8];
    #pragma unroll
    for (int i = 0; i < 8; i++)
        #pragma unroll
        for (int j = 0; j < 8; j++) acc[i][j] = 0.f;

    for (int k0 = 0; k0 < D; k0 += 32) {
        #pragma unroll
        for (int it = 0; it < 4; it++) {
            int v  = tid + it * 256;    // 0..1023 float4 slots
            int r  = v >> 3;            // row 0..127
            int kq = v & 7;             // float4 within 32-wide k chunk
            float4 fa = *reinterpret_cast<const float4*>(&X[(size_t)(rowBase + r) * D + k0 + kq * 4]);
            As[kq * 4 + 0][r] = fa.x; As[kq * 4 + 1][r] = fa.y;
            As[kq * 4 + 2][r] = fa.z; As[kq * 4 + 3][r] = fa.w;
            float4 fb = *reinterpret_cast<const float4*>(&X[(size_t)(colBase + r) * D + k0 + kq * 4]);
            Bs[kq * 4 + 0][r] = fb.x; Bs[kq * 4 + 1][r] = fb.y;
            Bs[kq * 4 + 2][r] = fb.z; Bs[kq * 4 + 3][r] = fb.w;
        }
        __syncthreads();

        #pragma unroll
        for (int k = 0; k < 32; k++) {
            float4 a0 = *reinterpret_cast<const float4*>(&As[k][ty * 8]);
            float4 a1 = *reinterpret_cast<const float4*>(&As[k][ty * 8 + 4]);
            float4 b0 = *reinterpret_cast<const float4*>(&Bs[k][tx * 8]);
            float4 b1 = *reinterpret_cast<const float4*>(&Bs[k][tx * 8 + 4]);
            float a[8] = {a0.x, a0.y, a0.z, a0.w, a1.x, a1.y, a1.z, a1.w};
            float b[8] = {b0.x, b0.y, b0.z, b0.w, b1.x, b1.y, b1.z, b1.w};
            #pragma unroll
            for (int i = 0; i < 8; i++)
                #pragma unroll
                for (int j = 0; j < 8; j++)
                    acc[i][j] = fmaf(a[i], b[j], acc[i][j]);
        }
        __syncthreads();
    }

    // targets for this tile
    int tr[8], tc[8];
    #pragma unroll
    for (int i = 0; i < 8; i++) tr[i] = g_t8[rowBase + ty * 8 + i];
    #pragma unroll
    for (int j = 0; j < 8; j++) tc[j] = g_t8[colBase + tx * 8 + j];

    // ---- row-direction reductions + normal (coalesced) store ----
    #pragma unroll
    for (int i = 0; i < 8; i++) {
        int row = rowBase + ty * 8 + i;
        float minp = BIGF, maxn = -BIGF;
        #pragma unroll
        for (int j = 0; j < 8; j++) {
            float s = acc[i][j];
            if (tr[i] == tc[j]) {
                if (s < 1.0f) minp = fminf(minp, s);
            } else {
                maxn = fmaxf(maxn, s);
            }
        }
        #pragma unroll
        for (int msk = 8; msk >= 1; msk >>= 1) {
            minp = fminf(minp, __shfl_xor_sync(0xFFFFFFFFu, minp, msk, 16));
            maxn = fmaxf(maxn, __shfl_xor_sync(0xFFFFFFFFu, maxn, msk, 16));
        }
        if (tx == 0) {
            atomicMin(&g_minpos[row], f2u(minp));
            atomicMax(&g_maxneg[row], f2u(maxn));
        }
        float* dst = &g_sim[(size_t)row * N + colBase + tx * 8];
        reinterpret_cast<float4*>(dst)[0] = make_float4(acc[i][0], acc[i][1], acc[i][2], acc[i][3]);
        reinterpret_cast<float4*>(dst)[1] = make_float4(acc[i][4], acc[i][5], acc[i][6], acc[i][7]);
    }

    // ---- column-direction reductions (feed rows colBase.. via symmetry) ----
    #pragma unroll
    for (int j = 0; j < 8; j++) {
        float cmin = BIGF, cmax = -BIGF;
        #pragma unroll
        for (int i = 0; i < 8; i++) {
            float s = acc[i][j];
            if (tr[i] == tc[j]) {
                if (s < 1.0f) cmin = fminf(cmin, s);
            } else {
                cmax = fmaxf(cmax, s);
            }
        }
        // combine the two ty-halves living in one warp (lane ^16 has same tx)
        cmin = fminf(cmin, __shfl_xor_sync(0xFFFFFFFFu, cmin, 16));
        cmax = fmaxf(cmax, __shfl_xor_sync(0xFFFFFFFFu, cmax, 16));
        if ((tid & 31) < 16) {   // one lane per (warp, tx)
            int col = colBase + tx * 8 + j;
            atomicMin(&g_minpos[col], f2u(cmin));
            atomicMax(&g_maxneg[col], f2u(cmax));
        }
    }

    // ---- transposed store via smem staging (reuse As), 32-column chunks ----
    float* Ts = &As[0][0];   // 32 x 128 floats
    #pragma unroll
    for (int cc = 0; cc < 4; cc++) {
        __syncthreads();
        if (tx >= cc * 4 && tx < cc * 4 + 4) {
            #pragma unroll
            for (int j = 0; j < 8; j++) {
                int lc = (tx - cc * 4) * 8 + j;            // local col in chunk
                *reinterpret_cast<float4*>(&Ts[lc * 128 + ty * 8]) =
                    make_float4(acc[0][j], acc[1][j], acc[2][j], acc[3][j]);
                *reinterpret_cast<float4*>(&Ts[lc * 128 + ty * 8 + 4]) =
                    make_float4(acc[4][j], acc[5][j], acc[6][j], acc[7][j]);
            }
        }
        __syncthreads();
        #pragma unroll
        for (int it = 0; it < 4; it++) {
            int v  = tid + it * 256;   // 1024 float4 slots
            int lc = v >> 5;           // 0..31
            int q  = v & 31;           // float4 within 128-wide row
            float4 val = *reinterpret_cast<const float4*>(&Ts[lc * 128 + q * 4]);
            *reinterpret_cast<float4*>(
                &g_sim[(size_t)(colBase + cc * 32 + lc) * N + rowBase + q * 4]) = val;
        }
    }
}

// ---------------- kernel: mining + masked exp sums; one block per row ----------------
__global__ __launch_bounds__(256) void k_mine(const float* __restrict__ margin,
                                              const float* __restrict__ weight,
                                              float* __restrict__ out, int out_size) {
    const int row = blockIdx.x;
    const int tid = threadIdx.x;

    const int   tr   = g_t8[row];
    const float m    = margin[row];
    const float w    = weight[row];
    const float minp = u2f(g_minpos[row]);
    const float maxn = u2f(g_maxneg[row]);

    const float4* srow4 = reinterpret_cast<const float4*>(&g_sim[(size_t)row * N]);
    const uchar4* t4    = reinterpret_cast<const uchar4*>(g_t8);

    // front-batched independent loads: 16 sim elements + 16 targets per thread
    float4 s0 = srow4[tid];
    float4 s1 = srow4[tid + 256];
    float4 s2 = srow4[tid + 512];
    float4 s3 = srow4[tid + 768];
    uchar4 c0 = t4[tid];
    uchar4 c1 = t4[tid + 256];
    uchar4 c2 = t4[tid + 512];
    uchar4 c3 = t4[tid + 768];

    float ps = 0.f, ns = 0.f;
    int ap = 0, an = 0;

    #define PROC(S, TJ)                                                     \
        do {                                                                \
            float s_ = (S);                                                 \
            if ((int)(TJ) == tr) {                                          \
                if (s_ < 1.0f && (maxn - s_ + m > 0.0f)) {                  \
                    ap++;                                                   \
                    ps += __expf(-BETA * (s_ * w - BASE));                  \
                }                                                           \
            } else if (s_ + m - minp > 0.0f) {                              \
                an++;                                                       \
                ns += __expf(ALPHA * (s_ * w - BASE));                      \
            }                                                               \
        } while (0)

    PROC(s0.x, c0.x); PROC(s0.y, c0.y); PROC(s0.z, c0.z); PROC(s0.w, c0.w);
    PROC(s1.x, c1.x); PROC(s1.y, c1.y); PROC(s1.z, c1.z); PROC(s1.w, c1.w);
    PROC(s2.x, c2.x); PROC(s2.y, c2.y); PROC(s2.z, c2.z); PROC(s2.w, c2.w);
    PROC(s3.x, c3.x); PROC(s3.y, c3.y); PROC(s3.z, c3.z); PROC(s3.w, c3.w);
    #undef PROC

    // deterministic reduction: butterfly in-warp, then fixed-order across 8 warps
    #pragma unroll
    for (int o = 16; o >= 1; o >>= 1) {
        ps += __shfl_xor_sync(0xFFFFFFFFu, ps, o);
        ns += __shfl_xor_sync(0xFFFFFFFFu, ns, o);
        ap += __shfl_xor_sync(0xFFFFFFFFu, ap, o);
        an += __shfl_xor_sync(0xFFFFFFFFu, an, o);
    }
    __shared__ float rps[8], rns[8];
    __shared__ int   rap[8], ran[8];
    int wid = tid >> 5;
    if ((tid & 31) == 0) { rps[wid] = ps; rns[wid] = ns; rap[wid] = ap; ran[wid] = an; }
    __syncthreads();

    if (tid == 0) {
        float Ps = 0.f, Ns = 0.f; int Ap = 0, An = 0;
        #pragma unroll
        for (int i = 0; i < 8; i++) { Ps += rps[i]; Ns += rns[i]; Ap += rap[i]; An += ran[i]; }
        int valid = (Ap + An) >= 1;
        float li = valid ? ((2.0f / BETA) * log1pf(Ps) + (2.0f / ALPHA) * log1pf(Ns)) : 0.0f;
        g_loss[row] = li;
        if (out_size >= 1 + 2 * N) {
            out[1 + row]     = valid ? (float)Ap : 0.0f;
            out[1 + N + row] = valid ? (float)An : 0.0f;
        }
    }
}

// ---------------- kernel: deterministic loss reduction ----------------
__global__ void k_reduce(float* __restrict__ out, int out_size) {
    __shared__ float s[1024];
    int t = threadIdx.x;
    float v = g_loss[t] + g_loss[t + 1024] + g_loss[t + 2048] + g_loss[t + 3072];
    s[t] = v;
    __syncthreads();
    #pragma unroll
    for (int o = 512; o >= 1; o >>= 1) {
        if (t < o) s[t] += s[t + o];
        __syncthreads();
    }
    if (t == 0 && out_size >= 1) out[0] = s[0] / (float)N;
}

// ---------------- launch ----------------
extern "C" void kernel_launch(void* const* d_in, const int* in_sizes, int n_in,
                              void* d_out, int out_size) {
    const float* X      = (const float*)d_in[0];
    const int*   tgt    = (const int*)d_in[1];
    const float* margin = (const float*)d_in[2];
    const float* weight = (const float*)d_in[3];
    float* out = (float*)d_out;

    k_prep<<<16, 256>>>(tgt);
    k_gemm<<<dim3(N / 128, N / 128), 256>>>(X);
    k_mine<<<N, 256>>>(margin, weight, out, out_size);
    k_reduce<<<1, 1024>>>(out, out_size);
}